// round 1
// baseline (speedup 1.0000x reference)
#include <cuda_runtime.h>
#include <math.h>
#include <stdint.h>

// Problem constants (fixed shapes from reference)
#define Bz   4
#define Sz   2048
#define Dz   1024
#define Hz   16
#define HDz  64
#define Mz   (Bz*Sz)                    // 8192
#define OUT_ELEMS   ((size_t)Mz*Dz)                 // 8,388,608
#define ATTN_ELEMS  ((size_t)Bz*Hz*Sz*Sz)           // 268,435,456

// Scratch (allocation-free: __device__ globals)
__device__ float g_q[Bz*Hz*Sz*HDz];
__device__ float g_k[Bz*Hz*Sz*HDz];
__device__ float g_v[Bz*Hz*Sz*HDz];
__device__ float g_ctx[Mz*Dz];

// ---------------------------------------------------------------------------
// SGEMM: C[M=8192, N=1024] = A[8192,1024] @ W[1024,1024] + bias
// MODE 0: plain row-major output.  MODE 1: head-split output [B,H,S,HD].
// 128x128 tile, BK=16, 256 threads, 8x8 per-thread microtile.
// ---------------------------------------------------------------------------
template<int MODE>
__global__ __launch_bounds__(256)
void sgemm_kernel(const float* __restrict__ A, const float* __restrict__ W,
                  const float* __restrict__ bias, float* __restrict__ C)
{
    __shared__ float As[16][132];   // transposed A tile, padded
    __shared__ float Bs[16][128];

    const int tid = threadIdx.x;
    const int bn  = blockIdx.x * 128;
    const int bm  = blockIdx.y * 128;

    float acc[8][8];
    #pragma unroll
    for (int i = 0; i < 8; i++)
        #pragma unroll
        for (int j = 0; j < 8; j++) acc[i][j] = 0.f;

    const int ar = tid >> 2;            // 0..63
    const int ac = (tid & 3) << 2;      // 0,4,8,12
    const int br = tid >> 5;            // 0..7
    const int bc = (tid & 31) << 2;     // 0..124
    const int tr = (tid >> 4) << 3;     // 0..120
    const int tc = (tid & 15) << 3;     // 0..120

    for (int k0 = 0; k0 < Dz; k0 += 16) {
        #pragma unroll
        for (int p = 0; p < 2; p++) {
            int row = ar + p * 64;
            float4 v = *(const float4*)&A[(size_t)(bm + row) * Dz + k0 + ac];
            As[ac + 0][row] = v.x; As[ac + 1][row] = v.y;
            As[ac + 2][row] = v.z; As[ac + 3][row] = v.w;
        }
        #pragma unroll
        for (int p = 0; p < 2; p++) {
            int row = br + p * 8;
            *(float4*)&Bs[row][bc] =
                *(const float4*)&W[(size_t)(k0 + row) * Dz + bn + bc];
        }
        __syncthreads();

        #pragma unroll
        for (int k = 0; k < 16; k++) {
            float a[8], b[8];
            *(float4*)&a[0] = *(float4*)&As[k][tr];
            *(float4*)&a[4] = *(float4*)&As[k][tr + 4];
            *(float4*)&b[0] = *(float4*)&Bs[k][tc];
            *(float4*)&b[4] = *(float4*)&Bs[k][tc + 4];
            #pragma unroll
            for (int i = 0; i < 8; i++)
                #pragma unroll
                for (int j = 0; j < 8; j++)
                    acc[i][j] += a[i] * b[j];
        }
        __syncthreads();
    }

    // epilogue
    #pragma unroll
    for (int i = 0; i < 8; i++) {
        const int gm = bm + tr + i;
        #pragma unroll
        for (int j = 0; j < 8; j += 4) {
            const int gn = bn + tc + j;
            float4 o;
            o.x = acc[i][j + 0] + bias[gn + 0];
            o.y = acc[i][j + 1] + bias[gn + 1];
            o.z = acc[i][j + 2] + bias[gn + 2];
            o.w = acc[i][j + 3] + bias[gn + 3];
            if (MODE == 0) {
                *(float4*)&C[(size_t)gm * Dz + gn] = o;
            } else {
                const int b = gm >> 11;        // / 2048
                const int s = gm & 2047;
                const int h = gn >> 6;
                const int d = gn & 63;
                *(float4*)&C[((size_t)(b * Hz + h) * Sz + s) * HDz + d] = o;
            }
        }
    }
}

// ---------------------------------------------------------------------------
// Fused attention per (b, h, 16-query-row tile):
//   scores (16x2048, exact softmax in SMEM) -> attn gmem write -> PV -> g_ctx
// SMEM: sQ [16][68], sKV [256][65], sS [16][2048]  = 201,984 B
// ---------------------------------------------------------------------------
#define SQ_STRIDE  68
#define SKV_STRIDE 65
#define ATTN_SMEM_BYTES ((16*SQ_STRIDE + 256*SKV_STRIDE + 16*Sz) * 4)

__device__ __forceinline__ void load_kv_chunk(const float* __restrict__ src,
                                              float* __restrict__ sKV,
                                              int c0, int tid)
{
    #pragma unroll
    for (int p = 0; p < 16; p++) {
        int idx = p * 1024 + tid * 4;       // 16384 floats = 256 rows x 64
        int row = idx >> 6, d = idx & 63;
        float4 v = *(const float4*)&src[(size_t)(c0 + row) * HDz + d];
        float* dst = &sKV[row * SKV_STRIDE + d];
        dst[0] = v.x; dst[1] = v.y; dst[2] = v.z; dst[3] = v.w;
    }
}

__global__ __launch_bounds__(256)
void attn_kernel(float* __restrict__ attn_out)
{
    extern __shared__ float smem[];
    float* sQ  = smem;                         // [16][68]
    float* sKV = smem + 16 * SQ_STRIDE;        // [256][65]
    float* sS  = sKV + 256 * SKV_STRIDE;       // [16][2048]

    const int tid = threadIdx.x;
    const int qt  = blockIdx.x;                // 0..127  (16 q rows each)
    const int bh  = blockIdx.y;                // 0..63
    const int b   = bh >> 4;
    const int h   = bh & 15;

    const float* Q = g_q + (size_t)bh * Sz * HDz;
    const float* K = g_k + (size_t)bh * Sz * HDz;
    const float* V = g_v + (size_t)bh * Sz * HDz;

    // load Q tile (16 x 64 = 1024 floats, exactly 4 per thread)
    {
        int idx = tid * 4;
        int row = idx >> 6, d = idx & 63;
        *(float4*)&sQ[row * SQ_STRIDE + d] =
            *(const float4*)&Q[(size_t)(qt * 16 + row) * HDz + d];
    }

    // ---- scores: sS[16][2048] = (Q Kt) * 1/8 ----
    const int rg = tid >> 6;       // 0..3  -> rows rg*4 .. rg*4+3
    const int tk = tid & 63;       // cols tk + {0,64,128,192}

    for (int c0 = 0; c0 < Sz; c0 += 256) {
        __syncthreads();                     // also covers sQ load on iter 0
        load_kv_chunk(K, sKV, c0, tid);
        __syncthreads();

        float acc[4][4];
        #pragma unroll
        for (int i = 0; i < 4; i++)
            #pragma unroll
            for (int j = 0; j < 4; j++) acc[i][j] = 0.f;

        #pragma unroll
        for (int k = 0; k < 64; k++) {
            float qv[4], kv[4];
            #pragma unroll
            for (int i = 0; i < 4; i++) qv[i] = sQ[(rg * 4 + i) * SQ_STRIDE + k];
            #pragma unroll
            for (int j = 0; j < 4; j++) kv[j] = sKV[(tk + j * 64) * SKV_STRIDE + k];
            #pragma unroll
            for (int i = 0; i < 4; i++)
                #pragma unroll
                for (int j = 0; j < 4; j++)
                    acc[i][j] += qv[i] * kv[j];
        }
        const float scale = 0.125f;   // 1/sqrt(64)
        #pragma unroll
        for (int i = 0; i < 4; i++)
            #pragma unroll
            for (int j = 0; j < 4; j++)
                sS[(rg * 4 + i) * Sz + c0 + tk + j * 64] = acc[i][j] * scale;
    }
    __syncthreads();

    // ---- exact softmax per row + attn write ----
    const int warp = tid >> 5, lane = tid & 31;
    for (int r = warp; r < 16; r += 8) {
        float* row = &sS[r * Sz];
        float m = -1e30f;
        for (int c = lane; c < Sz; c += 32) m = fmaxf(m, row[c]);
        #pragma unroll
        for (int o = 16; o; o >>= 1) m = fmaxf(m, __shfl_xor_sync(0xffffffffu, m, o));
        float sum = 0.f;
        for (int c = lane; c < Sz; c += 32) {
            float p = __expf(row[c] - m);
            row[c] = p;
            sum += p;
        }
        #pragma unroll
        for (int o = 16; o; o >>= 1) sum += __shfl_xor_sync(0xffffffffu, sum, o);
        const float inv = 1.f / sum;
        float* ga = attn_out ? attn_out + ((size_t)bh * Sz + qt * 16 + r) * Sz : (float*)0;
        for (int c = lane * 4; c < Sz; c += 128) {
            float4 p = *(float4*)&row[c];
            p.x *= inv; p.y *= inv; p.z *= inv; p.w *= inv;
            *(float4*)&row[c] = p;
            if (ga) *(float4*)&ga[c] = p;
        }
    }
    __syncthreads();

    // ---- PV: ctx[16][64] = attn @ V ----
    const int r4   = tid >> 6;           // row group 0..3
    const int dgrp = (tid >> 2) & 15;    // col group: d = dgrp*4 .. +3
    const int soff = tid & 3;            // s-phase split across 4 lanes

    float acc2[4][4];
    #pragma unroll
    for (int i = 0; i < 4; i++)
        #pragma unroll
        for (int j = 0; j < 4; j++) acc2[i][j] = 0.f;

    for (int c0 = 0; c0 < Sz; c0 += 256) {
        __syncthreads();
        load_kv_chunk(V, sKV, c0, tid);
        __syncthreads();
        for (int s = soff; s < 256; s += 4) {
            float av[4], vv[4];
            #pragma unroll
            for (int i = 0; i < 4; i++) av[i] = sS[(r4 * 4 + i) * Sz + c0 + s];
            #pragma unroll
            for (int j = 0; j < 4; j++) vv[j] = sKV[s * SKV_STRIDE + dgrp * 4 + j];
            #pragma unroll
            for (int i = 0; i < 4; i++)
                #pragma unroll
                for (int j = 0; j < 4; j++)
                    acc2[i][j] += av[i] * vv[j];
        }
    }
    // reduce the 4 s-phases (lanes l, l^1, l^2 share (r4,dgrp))
    #pragma unroll
    for (int i = 0; i < 4; i++)
        #pragma unroll
        for (int j = 0; j < 4; j++) {
            acc2[i][j] += __shfl_xor_sync(0xffffffffu, acc2[i][j], 1);
            acc2[i][j] += __shfl_xor_sync(0xffffffffu, acc2[i][j], 2);
        }
    {
        const int i    = soff;                       // each lane writes one row
        const int qrow = qt * 16 + r4 * 4 + i;
        float4 o;
        o.x = acc2[i][0]; o.y = acc2[i][1]; o.z = acc2[i][2]; o.w = acc2[i][3];
        *(float4*)&g_ctx[(size_t)(b * Sz + qrow) * Dz + h * HDz + dgrp * 4] = o;
    }
}

// ---------------------------------------------------------------------------
extern "C" void kernel_launch(void* const* d_in, const int* in_sizes, int n_in,
                              void* d_out, int out_size)
{
    const float* x  = (const float*)d_in[0];
    const float* wq = (const float*)d_in[1];
    const float* bq = (const float*)d_in[2];
    const float* wk = (const float*)d_in[3];
    const float* bk = (const float*)d_in[4];
    const float* wv = (const float*)d_in[5];
    const float* bv = (const float*)d_in[6];
    const float* wo = (const float*)d_in[7];
    const float* bo = (const float*)d_in[8];

    float* out = (float*)d_out;
    float* attn = ((size_t)out_size >= OUT_ELEMS + ATTN_ELEMS) ? out + OUT_ELEMS
                                                               : (float*)0;

    float *p_q, *p_k, *p_v, *p_ctx;
    cudaGetSymbolAddress((void**)&p_q,   g_q);
    cudaGetSymbolAddress((void**)&p_k,   g_k);
    cudaGetSymbolAddress((void**)&p_v,   g_v);
    cudaGetSymbolAddress((void**)&p_ctx, g_ctx);

    cudaFuncSetAttribute(attn_kernel,
                         cudaFuncAttributeMaxDynamicSharedMemorySize,
                         ATTN_SMEM_BYTES);

    dim3 gt(256);
    dim3 gg(Dz / 128, Mz / 128);

    // QKV projections (head-split outputs)
    sgemm_kernel<1><<<gg, gt>>>(x, wq, bq, p_q);
    sgemm_kernel<1><<<gg, gt>>>(x, wk, bk, p_k);
    sgemm_kernel<1><<<gg, gt>>>(x, wv, bv, p_v);

    // fused attention (scores + softmax + attn write + PV)
    dim3 ag(Sz / 16, Bz * Hz);
    attn_kernel<<<ag, gt, ATTN_SMEM_BYTES>>>(attn);

    // output projection
    sgemm_kernel<0><<<gg, gt>>>(p_ctx, wo, bo, out);
}

// round 3
// speedup vs baseline: 1.0000x; 1.0000x over previous
#include <cuda_runtime.h>
#include <math.h>
#include <stdint.h>

// Problem constants (fixed shapes from reference)
#define Bz   4
#define Sz   2048
#define Dz   1024
#define Hz   16
#define HDz  64
#define Mz   (Bz*Sz)                    // 8192
#define OUT_ELEMS   ((size_t)Mz*Dz)                 // 8,388,608
#define ATTN_ELEMS  ((size_t)Bz*Hz*Sz*Sz)           // 268,435,456

// Scratch (allocation-free: __device__ globals)
__device__ float g_q[Bz*Hz*Sz*HDz];
__device__ float g_k[Bz*Hz*Sz*HDz];
__device__ float g_v[Bz*Hz*Sz*HDz];
__device__ float g_ctx[Mz*Dz];

// ---------------------------------------------------------------------------
// SGEMM: C[M=8192, N=1024] = A[8192,1024] @ W[1024,1024] + bias
// MODE 0: plain row-major output.  MODE 1: head-split output [B,H,S,HD].
// 128x128 tile, BK=16, 256 threads, 8x8 per-thread microtile.
// ---------------------------------------------------------------------------
template<int MODE>
__global__ __launch_bounds__(256)
void sgemm_kernel(const float* __restrict__ A, const float* __restrict__ W,
                  const float* __restrict__ bias, float* __restrict__ C)
{
    __shared__ float As[16][132];   // transposed A tile, padded
    __shared__ float Bs[16][128];

    const int tid = threadIdx.x;
    const int bn  = blockIdx.x * 128;
    const int bm  = blockIdx.y * 128;

    float acc[8][8];
    #pragma unroll
    for (int i = 0; i < 8; i++)
        #pragma unroll
        for (int j = 0; j < 8; j++) acc[i][j] = 0.f;

    const int ar = tid >> 2;            // 0..63
    const int ac = (tid & 3) << 2;      // 0,4,8,12
    const int br = tid >> 5;            // 0..7
    const int bc = (tid & 31) << 2;     // 0..124
    const int tr = (tid >> 4) << 3;     // 0..120
    const int tc = (tid & 15) << 3;     // 0..120

    for (int k0 = 0; k0 < Dz; k0 += 16) {
        #pragma unroll
        for (int p = 0; p < 2; p++) {
            int row = ar + p * 64;
            float4 v = *(const float4*)&A[(size_t)(bm + row) * Dz + k0 + ac];
            As[ac + 0][row] = v.x; As[ac + 1][row] = v.y;
            As[ac + 2][row] = v.z; As[ac + 3][row] = v.w;
        }
        #pragma unroll
        for (int p = 0; p < 2; p++) {
            int row = br + p * 8;
            *(float4*)&Bs[row][bc] =
                *(const float4*)&W[(size_t)(k0 + row) * Dz + bn + bc];
        }
        __syncthreads();

        #pragma unroll
        for (int k = 0; k < 16; k++) {
            float a[8], b[8];
            *(float4*)&a[0] = *(float4*)&As[k][tr];
            *(float4*)&a[4] = *(float4*)&As[k][tr + 4];
            *(float4*)&b[0] = *(float4*)&Bs[k][tc];
            *(float4*)&b[4] = *(float4*)&Bs[k][tc + 4];
            #pragma unroll
            for (int i = 0; i < 8; i++)
                #pragma unroll
                for (int j = 0; j < 8; j++)
                    acc[i][j] += a[i] * b[j];
        }
        __syncthreads();
    }

    // epilogue
    #pragma unroll
    for (int i = 0; i < 8; i++) {
        const int gm = bm + tr + i;
        #pragma unroll
        for (int j = 0; j < 8; j += 4) {
            const int gn = bn + tc + j;
            float4 o;
            o.x = acc[i][j + 0] + bias[gn + 0];
            o.y = acc[i][j + 1] + bias[gn + 1];
            o.z = acc[i][j + 2] + bias[gn + 2];
            o.w = acc[i][j + 3] + bias[gn + 3];
            if (MODE == 0) {
                *(float4*)&C[(size_t)gm * Dz + gn] = o;
            } else {
                const int b = gm >> 11;        // / 2048
                const int s = gm & 2047;
                const int h = gn >> 6;
                const int d = gn & 63;
                *(float4*)&C[((size_t)(b * Hz + h) * Sz + s) * HDz + d] = o;
            }
        }
    }
}

// ---------------------------------------------------------------------------
// Fused attention per (b, h, 16-query-row tile):
//   scores (16x2048, exact softmax in SMEM) -> attn gmem write -> PV -> g_ctx
// SMEM: sQ [16][68], sKV [256][65], sS [16][2048]  = 201,984 B
// ---------------------------------------------------------------------------
#define SQ_STRIDE  68
#define SKV_STRIDE 65
#define ATTN_SMEM_BYTES ((16*SQ_STRIDE + 256*SKV_STRIDE + 16*Sz) * 4)

__device__ __forceinline__ void load_kv_chunk(const float* __restrict__ src,
                                              float* __restrict__ sKV,
                                              int c0, int tid)
{
    #pragma unroll
    for (int p = 0; p < 16; p++) {
        int idx = p * 1024 + tid * 4;       // 16384 floats = 256 rows x 64
        int row = idx >> 6, d = idx & 63;
        float4 v = *(const float4*)&src[(size_t)(c0 + row) * HDz + d];
        float* dst = &sKV[row * SKV_STRIDE + d];
        dst[0] = v.x; dst[1] = v.y; dst[2] = v.z; dst[3] = v.w;
    }
}

__global__ __launch_bounds__(256)
void attn_kernel(float* __restrict__ attn_out)
{
    extern __shared__ float smem[];
    float* sQ  = smem;                         // [16][68]
    float* sKV = smem + 16 * SQ_STRIDE;        // [256][65]
    float* sS  = sKV + 256 * SKV_STRIDE;       // [16][2048]

    const int tid = threadIdx.x;
    const int qt  = blockIdx.x;                // 0..127  (16 q rows each)
    const int bh  = blockIdx.y;                // 0..63
    const int b   = bh >> 4;
    const int h   = bh & 15;

    const float* Q = g_q + (size_t)bh * Sz * HDz;
    const float* K = g_k + (size_t)bh * Sz * HDz;
    const float* V = g_v + (size_t)bh * Sz * HDz;

    // load Q tile (16 x 64 = 1024 floats, exactly 4 per thread)
    {
        int idx = tid * 4;
        int row = idx >> 6, d = idx & 63;
        *(float4*)&sQ[row * SQ_STRIDE + d] =
            *(const float4*)&Q[(size_t)(qt * 16 + row) * HDz + d];
    }

    // ---- scores: sS[16][2048] = (Q Kt) * 1/8 ----
    const int rg = tid >> 6;       // 0..3  -> rows rg*4 .. rg*4+3
    const int tk = tid & 63;       // cols tk + {0,64,128,192}

    for (int c0 = 0; c0 < Sz; c0 += 256) {
        __syncthreads();                     // also covers sQ load on iter 0
        load_kv_chunk(K, sKV, c0, tid);
        __syncthreads();

        float acc[4][4];
        #pragma unroll
        for (int i = 0; i < 4; i++)
            #pragma unroll
            for (int j = 0; j < 4; j++) acc[i][j] = 0.f;

        #pragma unroll
        for (int k = 0; k < 64; k++) {
            float qv[4], kv[4];
            #pragma unroll
            for (int i = 0; i < 4; i++) qv[i] = sQ[(rg * 4 + i) * SQ_STRIDE + k];
            #pragma unroll
            for (int j = 0; j < 4; j++) kv[j] = sKV[(tk + j * 64) * SKV_STRIDE + k];
            #pragma unroll
            for (int i = 0; i < 4; i++)
                #pragma unroll
                for (int j = 0; j < 4; j++)
                    acc[i][j] += qv[i] * kv[j];
        }
        const float scale = 0.125f;   // 1/sqrt(64)
        #pragma unroll
        for (int i = 0; i < 4; i++)
            #pragma unroll
            for (int j = 0; j < 4; j++)
                sS[(rg * 4 + i) * Sz + c0 + tk + j * 64] = acc[i][j] * scale;
    }
    __syncthreads();

    // ---- exact softmax per row + attn write ----
    const int warp = tid >> 5, lane = tid & 31;
    for (int r = warp; r < 16; r += 8) {
        float* row = &sS[r * Sz];
        float m = -1e30f;
        for (int c = lane; c < Sz; c += 32) m = fmaxf(m, row[c]);
        #pragma unroll
        for (int o = 16; o; o >>= 1) m = fmaxf(m, __shfl_xor_sync(0xffffffffu, m, o));
        float sum = 0.f;
        for (int c = lane; c < Sz; c += 32) {
            float p = __expf(row[c] - m);
            row[c] = p;
            sum += p;
        }
        #pragma unroll
        for (int o = 16; o; o >>= 1) sum += __shfl_xor_sync(0xffffffffu, sum, o);
        const float inv = 1.f / sum;
        float* ga = attn_out ? attn_out + ((size_t)bh * Sz + qt * 16 + r) * Sz : (float*)0;
        for (int c = lane * 4; c < Sz; c += 128) {
            float4 p = *(float4*)&row[c];
            p.x *= inv; p.y *= inv; p.z *= inv; p.w *= inv;
            *(float4*)&row[c] = p;
            if (ga) *(float4*)&ga[c] = p;
        }
    }
    __syncthreads();

    // ---- PV: ctx[16][64] = attn @ V ----
    const int r4   = tid >> 6;           // row group 0..3
    const int dgrp = (tid >> 2) & 15;    // col group: d = dgrp*4 .. +3
    const int soff = tid & 3;            // s-phase split across 4 lanes

    float acc2[4][4];
    #pragma unroll
    for (int i = 0; i < 4; i++)
        #pragma unroll
        for (int j = 0; j < 4; j++) acc2[i][j] = 0.f;

    for (int c0 = 0; c0 < Sz; c0 += 256) {
        __syncthreads();
        load_kv_chunk(V, sKV, c0, tid);
        __syncthreads();
        for (int s = soff; s < 256; s += 4) {
            float av[4], vv[4];
            #pragma unroll
            for (int i = 0; i < 4; i++) av[i] = sS[(r4 * 4 + i) * Sz + c0 + s];
            #pragma unroll
            for (int j = 0; j < 4; j++) vv[j] = sKV[s * SKV_STRIDE + dgrp * 4 + j];
            #pragma unroll
            for (int i = 0; i < 4; i++)
                #pragma unroll
                for (int j = 0; j < 4; j++)
                    acc2[i][j] += av[i] * vv[j];
        }
    }
    // reduce the 4 s-phases (lanes l, l^1, l^2 share (r4,dgrp))
    #pragma unroll
    for (int i = 0; i < 4; i++)
        #pragma unroll
        for (int j = 0; j < 4; j++) {
            acc2[i][j] += __shfl_xor_sync(0xffffffffu, acc2[i][j], 1);
            acc2[i][j] += __shfl_xor_sync(0xffffffffu, acc2[i][j], 2);
        }
    {
        const int i    = soff;                       // each lane writes one row
        const int qrow = qt * 16 + r4 * 4 + i;
        float4 o;
        o.x = acc2[i][0]; o.y = acc2[i][1]; o.z = acc2[i][2]; o.w = acc2[i][3];
        *(float4*)&g_ctx[(size_t)(b * Sz + qrow) * Dz + h * HDz + dgrp * 4] = o;
    }
}

// ---------------------------------------------------------------------------
extern "C" void kernel_launch(void* const* d_in, const int* in_sizes, int n_in,
                              void* d_out, int out_size)
{
    const float* x  = (const float*)d_in[0];
    const float* wq = (const float*)d_in[1];
    const float* bq = (const float*)d_in[2];
    const float* wk = (const float*)d_in[3];
    const float* bk = (const float*)d_in[4];
    const float* wv = (const float*)d_in[5];
    const float* bv = (const float*)d_in[6];
    const float* wo = (const float*)d_in[7];
    const float* bo = (const float*)d_in[8];

    float* out = (float*)d_out;
    float* attn = ((size_t)out_size >= OUT_ELEMS + ATTN_ELEMS) ? out + OUT_ELEMS
                                                               : (float*)0;

    float *p_q, *p_k, *p_v, *p_ctx;
    cudaGetSymbolAddress((void**)&p_q,   g_q);
    cudaGetSymbolAddress((void**)&p_k,   g_k);
    cudaGetSymbolAddress((void**)&p_v,   g_v);
    cudaGetSymbolAddress((void**)&p_ctx, g_ctx);

    cudaFuncSetAttribute(attn_kernel,
                         cudaFuncAttributeMaxDynamicSharedMemorySize,
                         ATTN_SMEM_BYTES);

    dim3 gt(256);
    dim3 gg(Dz / 128, Mz / 128);

    // QKV projections (head-split outputs)
    sgemm_kernel<1><<<gg, gt>>>(x, wq, bq, p_q);
    sgemm_kernel<1><<<gg, gt>>>(x, wk, bk, p_k);
    sgemm_kernel<1><<<gg, gt>>>(x, wv, bv, p_v);

    // fused attention (scores + softmax + attn write + PV)
    dim3 ag(Sz / 16, Bz * Hz);
    attn_kernel<<<ag, gt, ATTN_SMEM_BYTES>>>(attn);

    // output projection
    sgemm_kernel<0><<<gg, gt>>>(p_ctx, wo, bo, out);
}